// round 11
// baseline (speedup 1.0000x reference)
#include <cuda_runtime.h>
#include <cstdint>

// EntropyCalculator: per-row histogram entropy.
//   x: [B, 64] int32 in [0,40)   out: [B,1] float32
// H = ln(64) - (ln2/64) * sum_v c_v log2(c_v)
//
// Persistent blocks + 2-deep cp.async ring (DRAM decoupled from smem phase)
// + FOUR DISTINCT sub-histogram objects (compiler-provable non-aliasing ->
// 4 interleaved RMW chains, depth 16 instead of 64) + MUFU epilogue (no LUT).

#define NT 128                    // threads = rows per tile
#define NW 10                     // 40 bins as 4x8-bit byte counts/word
#define TILE_W (NT * 64)          // 8192 words = 32 KB per ring slot
#define RING_BYTES (2 * TILE_W * 4)   // 64 KB dynamic

__global__ __launch_bounds__(NT, 2) void entropy_hist_kernel(
    const int4* __restrict__ x, float* __restrict__ out, int B, int ntiles)
{
    extern __shared__ uint32_t ring[];            // [slot0 | slot1]
    __shared__ uint32_t h0[NW * NT];              // 4 DISTINCT objects ->
    __shared__ uint32_t h1[NW * NT];              // independent RMW chains
    __shared__ uint32_t h2[NW * NT];
    __shared__ uint32_t h3[NW * NT];

    unsigned char* pc0 = (unsigned char*)h0;
    unsigned char* pc1 = (unsigned char*)h1;
    unsigned char* pc2 = (unsigned char*)h2;
    unsigned char* pc3 = (unsigned char*)h3;

    const int tid = threadIdx.x;
    const uint32_t t4 = (uint32_t)tid << 2;
    const uint32_t sb = (uint32_t)__cvta_generic_to_shared(ring);

    #pragma unroll
    for (int i = 0; i < NW; i++) {
        h0[i * NT + tid] = 0u; h1[i * NT + tid] = 0u;
        h2[i * NT + tid] = 0u; h3[i * NT + tid] = 0u;
    }

    // Balanced contiguous tile range for this block
    const int nb   = (int)gridDim.x;
    const int base = ntiles / nb, rem = ntiles % nb;
    const int my_n = base + ((int)blockIdx.x < rem);
    const int t0   = (int)blockIdx.x * base + min((int)blockIdx.x, rem);

    // Stage tile (t0+I) into ring slot (I&1): 16 x 16B cp.async per thread,
    // coalesced global reads, XOR-granule-swizzled smem destinations.
    #define STAGE(I)                                                           \
    do {                                                                       \
        const int4* gp_ = x + (size_t)(t0 + (I)) * (NT * 16);                  \
        const int el_ = min(NT, B - (t0 + (I)) * NT) * 16;                     \
        uint32_t db_ = sb + (uint32_t)(((I) & 1) * (TILE_W * 4));              \
        _Pragma("unroll")                                                      \
        for (int k_ = 0; k_ < 16; k_++) {                                      \
            int e_ = tid + k_ * NT;                                            \
            if (e_ < el_) {                                                    \
                int r_ = e_ >> 4, j_ = e_ & 15;                                \
                uint32_t d_ = db_ + (uint32_t)((r_ << 8) + ((j_ ^ (r_ & 7)) << 4)); \
                asm volatile("cp.async.cg.shared.global [%0], [%1], 16;"       \
                             :: "r"(d_), "l"(gp_ + e_));                       \
            }                                                                  \
        }                                                                      \
        asm volatile("cp.async.commit_group;" ::: "memory");                   \
    } while (0)

    if (my_n > 0) STAGE(0);

    for (int i = 0; i < my_n; i++) {
        if (i + 1 < my_n) {
            STAGE(i + 1);                                      // in flight during hist
            asm volatile("cp.async.wait_group 1;" ::: "memory");
        } else {
            asm volatile("cp.async.wait_group 0;" ::: "memory");
        }
        __syncthreads();               // tile i (all threads' copies) visible

        // Histogram own row: 16 LDS.128 (conflict-free via swizzle); each
        // word's 4 values go to 4 DISTINCT arrays -> interleaved chains.
        // NT=128 byte addr: bits [0:1]=v&3, [2:8]=tid, [9:12]=v>>2 (disjoint).
        const uint32_t* cur = ring + (i & 1) * TILE_W;
        const uint32_t trow = (uint32_t)tid << 6;
        const uint32_t sw   = (uint32_t)(tid & 7);
        #pragma unroll
        for (int j = 0; j < 16; j++) {
            uint4 q = *(const uint4*)&cur[trow + ((j ^ sw) << 2)];
            pc0[(((q.x & 0x3Cu) << 7) | (q.x & 3u)) + t4]++;
            pc1[(((q.y & 0x3Cu) << 7) | (q.y & 3u)) + t4]++;
            pc2[(((q.z & 0x3Cu) << 7) | (q.z & 3u)) + t4]++;
            pc3[(((q.w & 0x3Cu) << 7) | (q.w & 3u)) + t4]++;
        }

        // Merge sub-hists (byte sums <= 64: no carry crossing), re-zero,
        // entropy via MUFU (c * log2 c) - no LUT, no extra crossbar traffic.
        float acc = 0.0f;
        #pragma unroll
        for (int w_i = 0; w_i < NW; w_i++) {
            uint32_t w = h0[w_i * NT + tid] + h1[w_i * NT + tid]
                       + h2[w_i * NT + tid] + h3[w_i * NT + tid];
            h0[w_i * NT + tid] = 0u; h1[w_i * NT + tid] = 0u;
            h2[w_i * NT + tid] = 0u; h3[w_i * NT + tid] = 0u;
            #pragma unroll
            for (int b = 0; b < 4; b++) {
                float cf = (float)((w >> (8 * b)) & 0xFFu);
                acc += cf * __log2f(fmaxf(cf, 1.0f));   // c = 0,1 -> 0
            }
        }
        int row = (t0 + i) * NT + tid;
        if (row < B)
            out[row] = 4.1588830833596718565f - acc * 0.010830424696159069f;

        __syncthreads();   // slot (i&1) consumed + hists zeroed before restage
    }
    #undef STAGE
}

extern "C" void kernel_launch(void* const* d_in, const int* in_sizes, int n_in,
                              void* d_out, int out_size)
{
    const int4* x = (const int4*)d_in[0];
    float* out    = (float*)d_out;
    int B = in_sizes[0] / 64;
    int ntiles = (B + NT - 1) / NT;

    cudaFuncSetAttribute(entropy_hist_kernel,
                         cudaFuncAttributeMaxDynamicSharedMemorySize, RING_BYTES);

    int grid = 296;                 // 2 blocks/SM x 148 SMs (persistent)
    if (grid > ntiles) grid = ntiles;
    entropy_hist_kernel<<<grid, NT, RING_BYTES>>>(x, out, B, ntiles);
}

// round 12
// speedup vs baseline: 1.3439x; 1.3439x over previous
#include <cuda_runtime.h>
#include <cstdint>

// EntropyCalculator: per-row histogram entropy.
//   x: [B, 64] int32 in [0,40)   out: [B,1] float32
// H = ln(64) - (1/64) * sum_v c_v ln c_v
//
// Persistent blocks, 2-deep ring of BYTE-PACKED tiles (10 KB/slot, 4x less
// crossbar than raw), register prefetch of the full next tile issued before
// the hist phase (long overlap distance), split-2 private histograms
// (independent RMW chains), default-cached loads (input L2-resident across
// graph replays: 64 MiB < 126 MB L2).

#define NT 128                   // threads = rows per tile
#define PITCH 20                 // words per packed row (80 B: 4-phase-clean LDS.128)
#define SLOT_W (NT * PITCH)      // 2560 words = 10240 B per ring slot
#define RING_BYTES (2 * SLOT_W * 4)
#define NW 10                    // 40 bins as 4x8-bit byte counts per word

__global__ __launch_bounds__(NT, 4) void entropy_hist_kernel(
    const int4* __restrict__ x, float* __restrict__ out, int B, int ntiles)
{
    extern __shared__ uint32_t ring[];        // [slot0 | slot1], packed ids
    __shared__ uint32_t h0[NW * NT];          // two DISTINCT hist objects ->
    __shared__ uint32_t h1[NW * NT];          // two independent RMW chains
    __shared__ float    lut[72];              // lut[c] = c*ln(c)/64

    const int tid = threadIdx.x;
    const uint32_t t4 = (uint32_t)tid << 2;
    unsigned char* b0 = (unsigned char*)h0;
    unsigned char* b1 = (unsigned char*)h1;

    if (tid < 72) lut[tid] = (tid == 0) ? 0.0f
                           : (float)tid * logf((float)tid) * 0.015625f;
    #pragma unroll
    for (int i = 0; i < NW; i++) { h0[i * NT + tid] = 0u; h1[i * NT + tid] = 0u; }

    // Balanced contiguous tile range
    const int nb   = (int)gridDim.x;
    const int base = ntiles / nb, rem = ntiles % nb;
    const int my_n = base + ((int)blockIdx.x < rem);
    const int t0   = (int)blockIdx.x * base + min((int)blockIdx.x, rem);
    if (my_n == 0) return;

    // Staging geometry: thread t supplies packed word j = t&15 of rows
    // r = (t>>4) + 8k (global loads stay fully coalesced).
    const int jj = tid & 15;
    const int rb = tid >> 4;

    // ---- prologue: stage tile t0 into slot 0 -------------------------------
    {
        const int4* gp = x + (size_t)t0 * (NT * 16);
        #pragma unroll
        for (int k = 0; k < 16; k++) {
            int4 w = __ldg(&gp[tid + k * NT]);
            uint32_t a = __byte_perm((uint32_t)w.x, (uint32_t)w.y, 0x0040);
            uint32_t b = __byte_perm((uint32_t)w.z, (uint32_t)w.w, 0x0040);
            ring[(rb + 8 * k) * PITCH + jj] = __byte_perm(a, b, 0x5410);
        }
    }
    __syncthreads();

    for (int i = 0; i < my_n; i++) {
        const bool has_next = (i + 1 < my_n);

        // Prefetch ALL of tile i+1 into registers (no consumer until after the
        // hist loop -> ptxas hoists the 16 LDG.128s; ~full hist phase of overlap)
        int4 pf[16];
        if (has_next) {
            const int4* gp = x + (size_t)(t0 + i + 1) * (NT * 16);
            #pragma unroll
            for (int k = 0; k < 16; k++) pf[k] = __ldg(&gp[tid + k * NT]);
        }

        // ---- histogram own row: 4 LDS.128 (conflict-free, PITCH=20) +
        // 64 byte-RMWs alternating between two distinct arrays (depth 32 each).
        // byte addr bits: [0:1]=v&3, [2:8]=tid, [9:12]=v>>2 (disjoint, NT=128).
        const uint32_t* cur = ring + (i & 1) * SLOT_W + tid * PITCH;
        #pragma unroll
        for (int c = 0; c < 4; c++) {
            uint4 q = *(const uint4*)(cur + 4 * c);
            uint32_t ws[4] = {q.x, q.y, q.z, q.w};
            #pragma unroll
            for (int u = 0; u < 4; u++) {
                uint32_t p = ws[u];
                uint32_t v0 = __byte_perm(p, 0u, 0x4440);
                uint32_t v1 = __byte_perm(p, 0u, 0x4441);
                uint32_t v2 = __byte_perm(p, 0u, 0x4442);
                uint32_t v3 = __byte_perm(p, 0u, 0x4443);
                b0[(((v0 & 0x3Cu) << 7) | (v0 & 3u)) + t4]++;
                b1[(((v1 & 0x3Cu) << 7) | (v1 & 3u)) + t4]++;
                b0[(((v2 & 0x3Cu) << 7) | (v2 & 3u)) + t4]++;
                b1[(((v3 & 0x3Cu) << 7) | (v3 & 3u)) + t4]++;
            }
        }

        // ---- entropy via LUT; merge split hists (byte sums <= 64) + re-zero.
        // Hist columns are thread-private: no synchronization needed for them.
        float acc = 0.0f;
        #pragma unroll
        for (int wi = 0; wi < NW; wi++) {
            uint32_t w = h0[wi * NT + tid] + h1[wi * NT + tid];
            h0[wi * NT + tid] = 0u;
            h1[wi * NT + tid] = 0u;
            acc += lut[w & 0xFFu];
            acc += lut[(w >> 8) & 0xFFu];
            acc += lut[(w >> 16) & 0xFFu];
            acc += lut[w >> 24];
        }
        out[(size_t)(t0 + i) * NT + tid] = 4.1588830833596718565f - acc;

        __syncthreads();             // everyone done reading slot (i+1)&1's old data
        if (has_next) {
            uint32_t* dst = ring + ((i + 1) & 1) * SLOT_W;
            #pragma unroll
            for (int k = 0; k < 16; k++) {
                uint32_t a = __byte_perm((uint32_t)pf[k].x, (uint32_t)pf[k].y, 0x0040);
                uint32_t b = __byte_perm((uint32_t)pf[k].z, (uint32_t)pf[k].w, 0x0040);
                dst[(rb + 8 * k) * PITCH + jj] = __byte_perm(a, b, 0x5410);
            }
            __syncthreads();         // new tile visible before next iter's reads
        }
    }
}

extern "C" void kernel_launch(void* const* d_in, const int* in_sizes, int n_in,
                              void* d_out, int out_size)
{
    const int4* x = (const int4*)d_in[0];
    float* out    = (float*)d_out;
    int B = in_sizes[0] / 64;            // 262144 rows; B % 128 == 0
    int ntiles = B / NT;

    cudaFuncSetAttribute(entropy_hist_kernel,
                         cudaFuncAttributeMaxDynamicSharedMemorySize, RING_BYTES);

    int grid = 592;                      // 4 blocks/SM x 148 SMs, persistent
    if (grid > ntiles) grid = ntiles;
    entropy_hist_kernel<<<grid, NT, RING_BYTES>>>(x, out, B, ntiles);
}

// round 13
// speedup vs baseline: 1.3617x; 1.0133x over previous
#include <cuda_runtime.h>
#include <cstdint>

// EntropyCalculator: per-row histogram entropy.
//   x: [B, 64] int32 in [0,40)   out: [B,1] float32
// H = ln(64) - (ln2/64) * sum_v c_v log2(c_v)
//
// Fully WARP-AUTONOMOUS: no __syncthreads anywhere. Each warp stages its own
// 32 rows (coalesced LDG.128 -> pack -> warp-private smem tile), __syncwarp,
// then histograms (split-2 byte RMW, private columns) and computes entropy
// via MUFU. Warps desynchronize -> load/hist/epilogue phases overlap across
// warps by scheduler action instead of hand pipelining.

#define NT 256     // 8 warps x 32 rows = 256 rows per block
#define NW 10      // 40 bins as 4x8-bit byte counts per word

__global__ __launch_bounds__(NT, 6) void entropy_hist_kernel(
    const int4* __restrict__ x, float* __restrict__ out, int B)
{
    __shared__ uint32_t tile[NT * 17];   // 17-pitch packed rows (conflict-free reads)
    __shared__ uint32_t h0[NW * NT];     // two DISTINCT objects -> two independent
    __shared__ uint32_t h1[NW * NT];     // RMW chains (depth 32 each)

    const int tid  = threadIdx.x;
    const int lane = tid & 31;
    const int wrp  = tid >> 5;
    const uint32_t t4 = (uint32_t)tid << 2;
    unsigned char* b0 = (unsigned char*)h0;
    unsigned char* b1 = (unsigned char*)h1;

    // Zero own hist columns (thread-private -> no sync needed)
    #pragma unroll
    for (int i = 0; i < NW; i++) { h0[i * NT + tid] = 0u; h1[i * NT + tid] = 0u; }

    // ---- warp-local staging: 32 rows, 16 coalesced LDG.128 per lane --------
    const int row0 = blockIdx.x * NT + wrp * 32;     // this warp's 32 rows
    if (row0 >= B) return;
    const int4* gp = x + (size_t)row0 * 16;          // 32 rows x 16 int4 = 8 KB
    uint32_t* tw = tile + wrp * 32 * 17;             // warp-private tile section
    #pragma unroll
    for (int k = 0; k < 16; k++) {
        int e = k * 32 + lane;                       // coalesced within warp
        int4 v = __ldg(&gp[e]);
        uint32_t a = __byte_perm((uint32_t)v.x, (uint32_t)v.y, 0x0040);
        uint32_t b = __byte_perm((uint32_t)v.z, (uint32_t)v.w, 0x0040);
        int r = e >> 4, j = e & 15;
        tw[r * 17 + j] = __byte_perm(a, b, 0x5410);  // pitch-17: near-conflict-free
    }
    __syncwarp();                                    // warp-scope visibility only

    // ---- histogram own row (lane): 16 scalar LDS (17-pitch: banks form a
    // permutation across lanes), 64 byte-RMWs split across two arrays.
    // NT=256 byte addr bits: [0:1]=v&3, [2:9]=tid, [10:13]=v>>2 (disjoint).
    const uint32_t* my = tw + lane * 17;
    #pragma unroll
    for (int j = 0; j < 16; j++) {
        uint32_t p = my[j];
        uint32_t v0 = __byte_perm(p, 0u, 0x4440);
        uint32_t v1 = __byte_perm(p, 0u, 0x4441);
        uint32_t v2 = __byte_perm(p, 0u, 0x4442);
        uint32_t v3 = __byte_perm(p, 0u, 0x4443);
        b0[(((v0 & 0x3Cu) << 8) | (v0 & 3u)) + t4]++;
        b1[(((v1 & 0x3Cu) << 8) | (v1 & 3u)) + t4]++;
        b0[(((v2 & 0x3Cu) << 8) | (v2 & 3u)) + t4]++;
        b1[(((v3 & 0x3Cu) << 8) | (v3 & 3u)) + t4]++;
    }

    // ---- entropy epilogue: merge split hists (byte sums <= 64, no carry
    // crossing) and accumulate c*log2(c) on the MUFU pipe (no LUT, no sync).
    float acc = 0.0f;
    #pragma unroll
    for (int i = 0; i < NW; i++) {
        uint32_t w = h0[i * NT + tid] + h1[i * NT + tid];
        #pragma unroll
        for (int b = 0; b < 4; b++) {
            float cf = (float)((w >> (8 * b)) & 0xFFu);
            acc += cf * __log2f(fmaxf(cf, 1.0f));    // c = 0,1 -> 0
        }
    }
    int row = row0 + lane;
    if (row < B)
        out[row] = 4.1588830833596718565f - acc * 0.010830424696159069f;
}

extern "C" void kernel_launch(void* const* d_in, const int* in_sizes, int n_in,
                              void* d_out, int out_size)
{
    const int4* x = (const int4*)d_in[0];
    float* out    = (float*)d_out;
    int B = in_sizes[0] / 64;
    int grid = (B + NT - 1) / NT;
    entropy_hist_kernel<<<grid, NT>>>(x, out, B);
}